// round 15
// baseline (speedup 1.0000x reference)
#include <cuda_runtime.h>
#include <cuda_fp16.h>
#include <cstdint>

#define BATCH    1024
#define EMBED    128
#define ITEMS    262144
#define TOPK     100
#define TM       32               // tile-max granularity (items)
#define NTM      (ITEMS/TM)       // 8192 tile maxima per row

#define NTILE    64               // items per GEMM N-tile
#define TPB      16               // N-tiles per CTA
#define GMB      128              // M rows per CTA

__device__ __half g_logits[(size_t)BATCH * ITEMS];
__device__ float  g_tilemax[(size_t)BATCH * NTM];
__device__ __half g_whf[(size_t)ITEMS * EMBED];   // pre-converted w (fp16)

// ---------------------------------------------------------------------------
__device__ __forceinline__ uint32_t smem_u32(const void* p) {
    uint32_t a;
    asm("{ .reg .u64 t; cvta.to.shared.u64 t, %1; cvt.u32.u64 %0, t; }"
        : "=r"(a) : "l"(p));
    return a;
}
__device__ __forceinline__ uint32_t packhf(float lo, float hi) {
    uint32_t r;
    asm("cvt.rn.f16x2.f32 %0, %1, %2;" : "=r"(r) : "f"(hi), "f"(lo));
    return r;
}

#define LDSM4(r0, r1, r2, r3, a)                                              \
    asm volatile("ldmatrix.sync.aligned.m8n8.x4.shared.b16 {%0,%1,%2,%3}, [%4];" \
        : "=r"(r0), "=r"(r1), "=r"(r2), "=r"(r3) : "r"(a))

#define STSM4(a, r0, r1, r2, r3)                                              \
    asm volatile("stmatrix.sync.aligned.m8n8.x4.shared.b16 [%0], {%1,%2,%3,%4};" \
        :: "r"(a), "r"(r0), "r"(r1), "r"(r2), "r"(r3) : "memory")

#define MMA_F16(d, A, b0, b1)                                                 \
    asm volatile("mma.sync.aligned.m16n8k16.row.col.f32.f16.f16.f32 "         \
        "{%0,%1,%2,%3}, {%4,%5,%6,%7}, {%8,%9}, {%0,%1,%2,%3};"               \
        : "+f"((d)[0]), "+f"((d)[1]), "+f"((d)[2]), "+f"((d)[3])              \
        : "r"((A)[0]), "r"((A)[1]), "r"((A)[2]), "r"((A)[3]),                 \
          "r"(b0), "r"(b1))

#define CP_ASYNC16(dst, src)                                                  \
    asm volatile("cp.async.cg.shared.global [%0], [%1], 16;"                  \
        :: "r"(dst), "l"(src) : "memory")
#define CP_COMMIT()  asm volatile("cp.async.commit_group;" ::: "memory")
#define CP_WAIT0()   asm volatile("cp.async.wait_group 0;" ::: "memory")
#define CP_WAIT1()   asm volatile("cp.async.wait_group 1;" ::: "memory")

// ---------------------------------------------------------------------------
// One-time w conversion: fp32 -> fp16 (row-major). Separate kernel — at the
// DRAM roof (27us); round-12 proved fusing it into the GEMM grid regresses.
// ---------------------------------------------------------------------------
__global__ __launch_bounds__(256)
void convert_w(const float* __restrict__ w)
{
    const size_t i = (size_t)blockIdx.x * blockDim.x + threadIdx.x; // 8 floats
    const float4* w4 = (const float4*)w;
    const float4 a = w4[i * 2], b = w4[i * 2 + 1];
    ((uint4*)g_whf)[i] = make_uint4(packhf(a.x, a.y), packhf(a.z, a.w),
                                    packhf(b.x, b.y), packhf(b.z, b.w));
}

// ---------------------------------------------------------------------------
// Screening GEMM (2 CTAs/SM): fp16 HMMA, 128(M) x 64(N) x 16 tiles,
// 8 warps (4M x 2N), warp tile 32x32. A resident 32KB; B triple-buffered
// 3x16KB cp.async (wait_group 1); stage double-buffered 2x16KB.
// Measured ~248us = HMMA-issue floor (16.78M HMMA / 592 SMSP x rt 16).
// ---------------------------------------------------------------------------
#define SM_B      32768
#define SM_STAGE  81920
#define BTILE_SZ  16384
#define STAGE_SZ  16384
#define SM_TOTAL  114688

__global__ __launch_bounds__(256, 2)
void gemm_screen(const float* __restrict__ x)
{
    extern __shared__ char smem[];
    const uint32_t sb = smem_u32(smem);
    const int tid  = threadIdx.x;
    const int lane = tid & 31;
    const int wid  = tid >> 5;
    const int rowBase   = blockIdx.x * GMB;
    const int itemBase0 = blockIdx.y * (NTILE * TPB);

    int bR[4], bC[4];
    uint32_t bDst[4];
    #pragma unroll
    for (int i = 0; i < 4; i++) {
        const int flat = tid + 256 * i;
        bR[i] = flat >> 4;
        bC[i] = flat & 15;
        bDst[i] = sb + SM_B + bR[i] * 256 + ((bC[i] ^ (bR[i] & 7)) << 4);
    }

    // ---- Stage A (128x128): fp32 -> fp16, 16B-chunk XOR swizzle ----
    const float4* x4 = (const float4*)(x + (size_t)rowBase * EMBED);
    #pragma unroll
    for (int i = 0; i < 8; i++) {
        const int flat = tid + 256 * i;
        const int r = flat >> 4, c = flat & 15;
        const int swc = c ^ (r & 7);
        float4 a0 = x4[flat * 2], a1 = x4[flat * 2 + 1];
        uint4 pa = make_uint4(packhf(a0.x, a0.y), packhf(a0.z, a0.w),
                              packhf(a1.x, a1.y), packhf(a1.z, a1.w));
        *(uint4*)(smem + r * 256 + swc * 16) = pa;
    }

    // ---- cp.async B tiles 0 and 1 (two groups in flight) ----
    #pragma unroll
    for (int i = 0; i < 4; i++) {
        const char* src = (const char*)g_whf
                        + (size_t)(itemBase0 + bR[i]) * 256 + bC[i] * 16;
        CP_ASYNC16(bDst[i], src);
    }
    CP_COMMIT();
    #pragma unroll
    for (int i = 0; i < 4; i++) {
        const char* src = (const char*)g_whf
                        + (size_t)(itemBase0 + NTILE + bR[i]) * 256 + bC[i] * 16;
        CP_ASYNC16(bDst[i] + BTILE_SZ, src);
    }
    CP_COMMIT();

    const int wm = wid >> 1;
    const int wn = wid & 1;
    const int la7  = lane & 7;
    const int lg8  = (lane >> 3) & 1;
    const int cgrp = lane >> 4;

    int Aoff[2], Asw[2];
    #pragma unroll
    for (int a = 0; a < 2; a++) {
        const int rr = wm * 32 + a * 16 + la7 + lg8 * 8;
        Aoff[a] = rr * 256;  Asw[a] = rr & 7;
    }
    int BoffR[2], Bsw[2];
    #pragma unroll
    for (int p = 0; p < 2; p++) {
        const int nr = wn * 32 + p * 16 + la7 + lg8 * 8;
        BoffR[p] = nr * 256;  Bsw[p] = nr & 7;
    }
    const int smRow0 = wm * 32 + lg8 * 8 + la7;
    const int chunk0 = wn * 4 + (lane >> 4);

    for (int n = 0; n < TPB; n++) {
        const int cur3 = n % 3;
        const int itemBase = itemBase0 + n * NTILE;

        if (n == TPB - 1) CP_WAIT0(); else CP_WAIT1();
        __syncthreads();

        if (n + 2 < TPB) {
            const uint32_t flip = ((n + 2) % 3) * BTILE_SZ;
            #pragma unroll
            for (int i = 0; i < 4; i++) {
                const char* src = (const char*)g_whf
                                + (size_t)(itemBase + 2 * NTILE + bR[i]) * 256
                                + bC[i] * 16;
                CP_ASYNC16(bDst[i] + flip, src);
            }
            CP_COMMIT();
        }

        float d[2][4][4];
        #pragma unroll
        for (int a = 0; a < 2; a++)
            #pragma unroll
            for (int b = 0; b < 4; b++)
                #pragma unroll
                for (int q = 0; q < 4; q++) d[a][b][q] = 0.0f;

        const uint32_t bBase = sb + SM_B + cur3 * BTILE_SZ;
        #pragma unroll
        for (int ks = 0; ks < 8; ks++) {
            const int kc = ks * 2 + cgrp;
            uint32_t A[2][4], B[2][4];
            #pragma unroll
            for (int a = 0; a < 2; a++)
                LDSM4(A[a][0], A[a][1], A[a][2], A[a][3],
                      sb + Aoff[a] + ((kc ^ Asw[a]) << 4));
            #pragma unroll
            for (int p = 0; p < 2; p++)
                LDSM4(B[p][0], B[p][1], B[p][2], B[p][3],
                      bBase + BoffR[p] + ((kc ^ Bsw[p]) << 4));
            #pragma unroll
            for (int a = 0; a < 2; a++)
                #pragma unroll
                for (int b = 0; b < 4; b++)
                    MMA_F16(d[a][b], A[a], B[b >> 1][b & 1], B[b >> 1][(b & 1) + 2]);
        }

        const uint32_t stageBase = sb + SM_STAGE + (n & 1) * STAGE_SZ;
        const int colW = itemBase + wn * 32;
        #pragma unroll
        for (int a = 0; a < 2; a++) {
            uint32_t p[8];
            float m1 = -3.402823466e+38f, m2 = m1;
            #pragma unroll
            for (int b = 0; b < 4; b++) {
                p[b * 2 + 0] = packhf(d[a][b][0], d[a][b][1]);
                p[b * 2 + 1] = packhf(d[a][b][2], d[a][b][3]);
                m1 = fmaxf(m1, fmaxf(d[a][b][0], d[a][b][1]));
                m2 = fmaxf(m2, fmaxf(d[a][b][2], d[a][b][3]));
            }
            const int row = smRow0 + a * 16;
            #pragma unroll
            for (int bp = 0; bp < 2; bp++) {
                const int ch = chunk0 + bp * 2;
                const uint32_t addr = stageBase + row * 128
                                    + ((ch ^ (row & 7)) << 4);
                STSM4(addr, p[bp * 4 + 0], p[bp * 4 + 1],
                            p[bp * 4 + 2], p[bp * 4 + 3]);
            }
            m1 = fmaxf(m1, __shfl_xor_sync(0xFFFFFFFFu, m1, 1));
            m1 = fmaxf(m1, __shfl_xor_sync(0xFFFFFFFFu, m1, 2));
            m2 = fmaxf(m2, __shfl_xor_sync(0xFFFFFFFFu, m2, 1));
            m2 = fmaxf(m2, __shfl_xor_sync(0xFFFFFFFFu, m2, 2));
            if ((lane & 3) == 0) {
                const int r1 = rowBase + wm * 32 + a * 16 + (lane >> 2);
                const int grp = colW / TM;
                g_tilemax[(size_t)r1 * NTM + grp]       = m1;
                g_tilemax[(size_t)(r1 + 8) * NTM + grp] = m2;
            }
        }

        if (n >= 1) {
            const char* prev = smem + SM_STAGE + ((n - 1) & 1) * STAGE_SZ;
            const int ib = itemBase - NTILE;
            #pragma unroll
            for (int i = 0; i < 4; i++) {
                const int flat = tid + 256 * i;
                const int r = flat >> 3, c = flat & 7;
                const uint4 v = *(const uint4*)(prev + r * 128
                                                + ((c ^ (r & 7)) << 4));
                *(uint4*)((char*)g_logits
                          + ((size_t)(rowBase + r) * ITEMS + ib) * 2
                          + c * 16) = v;
            }
        }
    }

    __syncthreads();
    {
        const char* prev = smem + SM_STAGE + ((TPB - 1) & 1) * STAGE_SZ;
        const int ib = itemBase0 + (TPB - 1) * NTILE;
        #pragma unroll
        for (int i = 0; i < 4; i++) {
            const int flat = tid + 256 * i;
            const int r = flat >> 3, c = flat & 7;
            const uint4 v = *(const uint4*)(prev + r * 128
                                            + ((c ^ (r & 7)) << 4));
            *(uint4*)((char*)g_logits
                      + ((size_t)(rowBase + r) * ITEMS + ib) * 2
                      + c * 16) = v;
        }
    }
}

// ---------------------------------------------------------------------------
// Top-k: 256 threads, __launch_bounds__(256, 8) -> full RF = 8 CTAs/SM ->
// 1184 resident CTAs >= 1024 -> SINGLE WAVE; all serial latency phases
// overlap across 8 resident rows and the tail wave disappears.
// fp16 screen error bound B = 2^-11 * ||x||2 * 0.1*sqrt(128); eps = 2.1*B;
// threshold via bisection (16 iters) on 256 group maxima (32 tiles each) with
// invariant cnt(>= lo) >= 100; thr = lo - 1.05*eps; exact sequential-fmaf
// rescore; 64-bit key bitonic sort (value desc, index asc on ties).
// ---------------------------------------------------------------------------
#define TKT  256
#define CMAX 1024

__device__ __forceinline__ unsigned int fkey(float f) {
    unsigned int b = __float_as_uint(f);
    return b ^ ((b & 0x80000000u) ? 0xFFFFFFFFu : 0x80000000u);
}

__device__ __forceinline__ int wagg_append(int* ctr, bool pred, int ln) {
    const unsigned mask = __ballot_sync(0xFFFFFFFFu, pred);
    if (!pred) return -1;
    const int leader = __ffs(mask) - 1;
    int base = 0;
    if (ln == leader) base = atomicAdd(ctr, __popc(mask));
    base = __shfl_sync(mask, base, leader);
    return base + __popc(mask & ((1u << ln) - 1u));
}

__global__ __launch_bounds__(TKT, 8)
void topk_kernel(const float* __restrict__ x, const float* __restrict__ w,
                 float* __restrict__ out)
{
    __shared__ float              s_x[EMBED];
    __shared__ float              s_wmax[8], s_wmin[8];
    __shared__ int                s_tiles[CMAX];
    __shared__ int                s_cidx[CMAX];
    __shared__ unsigned long long s_cand[CMAX];
    __shared__ int   s_nt, s_nc;
    __shared__ float s_eps;

    const int row = blockIdx.x;
    const int tid = threadIdx.x;
    const int wrp = tid >> 5, ln = tid & 31;
    const float4* tm4 = (const float4*)(g_tilemax + (size_t)row * NTM);

    if (tid < EMBED) s_x[tid] = x[(size_t)row * EMBED + tid];
    if (tid == 0) { s_nt = 0; s_nc = 0; }
    __syncthreads();

    if (tid < 32) {
        float ss = 0.0f;
        #pragma unroll
        for (int j = 0; j < 4; j++) { float v = s_x[tid * 4 + j]; ss += v * v; }
        #pragma unroll
        for (int o = 16; o > 0; o >>= 1) ss += __shfl_xor_sync(0xFFFFFFFFu, ss, o);
        if (tid == 0) s_eps = 1.05f * (1.0f / 1024.0f) * sqrtf(ss) * 1.1313708f;
    }

    // per-thread group max over 32 contiguous tile-maxima (8 x LDG.128)
    float m = -3.402823466e+38f;
    #pragma unroll
    for (int j = 0; j < 8; j++) {
        const float4 v = tm4[tid * 8 + j];
        m = fmaxf(m, fmaxf(fmaxf(v.x, v.y), fmaxf(v.z, v.w)));
    }
    float wmx = m, wmn = m;
    #pragma unroll
    for (int o = 16; o > 0; o >>= 1) {
        wmx = fmaxf(wmx, __shfl_xor_sync(0xFFFFFFFFu, wmx, o));
        wmn = fminf(wmn, __shfl_xor_sync(0xFFFFFFFFu, wmn, o));
    }
    if (ln == 0) { s_wmax[wrp] = wmx; s_wmin[wrp] = wmn; }
    __syncthreads();
    float hi = s_wmax[0], lo = s_wmin[0];
    #pragma unroll
    for (int j = 1; j < 8; j++) {
        hi = fmaxf(hi, s_wmax[j]);
        lo = fminf(lo, s_wmin[j]);
    }

    // bisection: invariant cnt(m >= lo) >= 100; a lower lo only ADDS
    // candidates (still exact); resolution after 16 iters << eps
    #pragma unroll
    for (int it = 0; it < 16; it++) {
        const float mid = 0.5f * (lo + hi);
        const int cnt = __syncthreads_count(m >= mid);
        if (cnt >= TOPK) lo = mid; else hi = mid;
    }
    const float thr = lo - 1.05f * s_eps - 1e-6f;

    // qualifying tiles (warp-aggregated append)
    #pragma unroll
    for (int j = 0; j < 8; j++) {
        const float4 v = tm4[tid * 8 + j];
        const int base = tid * 32 + j * 4;
        #pragma unroll
        for (int c = 0; c < 4; c++) {
            const float tv = (c == 0) ? v.x : (c == 1) ? v.y : (c == 2) ? v.z : v.w;
            const bool q = (tv >= thr);
            const int p = wagg_append(&s_nt, q, ln);
            if (q && p < CMAX) s_tiles[p] = base + c;
        }
    }
    __syncthreads();
    const int ntl = s_nt < CMAX ? s_nt : CMAX;

    // candidates within qualifying tiles: 4-way MLP over tiles per warp
    const __half* lg = g_logits + (size_t)row * ITEMS;
    const int NW = TKT / 32;
    int i = wrp;
    for (; i + 3 * NW < ntl; i += 4 * NW) {
        int t0 = s_tiles[i],          t1 = s_tiles[i + NW];
        int t2 = s_tiles[i + 2 * NW], t3 = s_tiles[i + 3 * NW];
        float v0 = __half2float(lg[t0 * TM + ln]);
        float v1 = __half2float(lg[t1 * TM + ln]);
        float v2 = __half2float(lg[t2 * TM + ln]);
        float v3 = __half2float(lg[t3 * TM + ln]);
        bool q; int p;
        q = (v0 >= thr); p = wagg_append(&s_nc, q, ln);
        if (q && p < CMAX) s_cidx[p] = t0 * TM + ln;
        q = (v1 >= thr); p = wagg_append(&s_nc, q, ln);
        if (q && p < CMAX) s_cidx[p] = t1 * TM + ln;
        q = (v2 >= thr); p = wagg_append(&s_nc, q, ln);
        if (q && p < CMAX) s_cidx[p] = t2 * TM + ln;
        q = (v3 >= thr); p = wagg_append(&s_nc, q, ln);
        if (q && p < CMAX) s_cidx[p] = t3 * TM + ln;
    }
    for (; i < ntl; i += NW) {
        const int idx = s_tiles[i] * TM + ln;
        const float v = __half2float(lg[idx]);
        const bool q = (v >= thr);
        const int p = wagg_append(&s_nc, q, ln);
        if (q && p < CMAX) s_cidx[p] = idx;
    }
    __syncthreads();
    const int C = s_nc < CMAX ? s_nc : CMAX;

    // exact rescore: one thread per candidate, sequential fmaf k=0..127
    for (int i2 = tid; i2 < C; i2 += TKT) {
        const int idx = s_cidx[i2];
        const float* wr = w + (size_t)idx * EMBED;
        float s = 0.0f;
        #pragma unroll 8
        for (int k4 = 0; k4 < EMBED / 4; k4++) {
            const float4 wv = ((const float4*)wr)[k4];
            s = fmaf(s_x[k4 * 4 + 0], wv.x, s);
            s = fmaf(s_x[k4 * 4 + 1], wv.y, s);
            s = fmaf(s_x[k4 * 4 + 2], wv.z, s);
            s = fmaf(s_x[k4 * 4 + 3], wv.w, s);
        }
        s_cand[i2] = ((unsigned long long)fkey(s) << 32) |
                     (unsigned int)(~(unsigned int)idx);
    }
    __syncthreads();

    int P = 128;
    while (P < C) P <<= 1;
    for (int i2 = tid; i2 < P; i2 += TKT)
        if (i2 >= C) s_cand[i2] = 0ULL;
    __syncthreads();

    // bitonic sort P 64-bit keys desc (value desc, index asc on ties)
    for (int k = 2; k <= P; k <<= 1) {
        for (int j = k >> 1; j > 0; j >>= 1) {
            for (int i2 = tid; i2 < P; i2 += TKT) {
                const int ixj = i2 ^ j;
                if (ixj > i2) {
                    const bool desc = ((i2 & k) == 0);
                    const unsigned long long a = s_cand[i2], b = s_cand[ixj];
                    if (desc ? (a < b) : (a > b)) { s_cand[i2] = b; s_cand[ixj] = a; }
                }
            }
            __syncthreads();
        }
    }

    if (tid < TOPK) {
        const unsigned int low = (unsigned int)s_cand[tid];
        out[(size_t)row * TOPK + tid] = (float)(~low);
    }
}

// ---------------------------------------------------------------------------
extern "C" void kernel_launch(void* const* d_in, const int* in_sizes, int n_in,
                              void* d_out, int out_size)
{
    const float* x = nullptr;
    const float* w = nullptr;
    for (int i = 0; i < n_in; i++) {
        if (in_sizes[i] == BATCH * EMBED)      x = (const float*)d_in[i];
        else if (in_sizes[i] == ITEMS * EMBED) w = (const float*)d_in[i];
    }
    float* out = (float*)d_out;

    static bool attr_set = false;
    if (!attr_set) {
        cudaFuncSetAttribute(gemm_screen,
                             cudaFuncAttributeMaxDynamicSharedMemorySize, SM_TOTAL);
        attr_set = true;
    }

    convert_w<<<(ITEMS * EMBED / 8) / 256, 256>>>(w);
    dim3 grid(BATCH / GMB, ITEMS / (NTILE * TPB));   // (8, 256)
    gemm_screen<<<grid, 256, SM_TOTAL>>>(x);
    topk_kernel<<<BATCH, TKT>>>(x, w, out);
}

// round 16
// speedup vs baseline: 1.0161x; 1.0161x over previous
#include <cuda_runtime.h>
#include <cuda_fp16.h>
#include <cstdint>

#define BATCH    1024
#define EMBED    128
#define ITEMS    262144
#define TOPK     100
#define TM       32               // tile-max granularity (items)
#define NTM      (ITEMS/TM)       // 8192 tile maxima per row

#define NTILE    64               // items per GEMM N-tile
#define TPB      16               // N-tiles per CTA
#define GMB      128              // M rows per CTA

__device__ __half g_logits[(size_t)BATCH * ITEMS];
__device__ float  g_tilemax[(size_t)BATCH * NTM];
__device__ __half g_whf[(size_t)ITEMS * EMBED];   // pre-converted w (fp16)

// ---------------------------------------------------------------------------
__device__ __forceinline__ uint32_t smem_u32(const void* p) {
    uint32_t a;
    asm("{ .reg .u64 t; cvta.to.shared.u64 t, %1; cvt.u32.u64 %0, t; }"
        : "=r"(a) : "l"(p));
    return a;
}
__device__ __forceinline__ uint32_t packhf(float lo, float hi) {
    uint32_t r;
    asm("cvt.rn.f16x2.f32 %0, %1, %2;" : "=r"(r) : "f"(hi), "f"(lo));
    return r;
}

#define LDSM4(r0, r1, r2, r3, a)                                              \
    asm volatile("ldmatrix.sync.aligned.m8n8.x4.shared.b16 {%0,%1,%2,%3}, [%4];" \
        : "=r"(r0), "=r"(r1), "=r"(r2), "=r"(r3) : "r"(a))

#define STSM4(a, r0, r1, r2, r3)                                              \
    asm volatile("stmatrix.sync.aligned.m8n8.x4.shared.b16 [%0], {%1,%2,%3,%4};" \
        :: "r"(a), "r"(r0), "r"(r1), "r"(r2), "r"(r3) : "memory")

#define MMA_F16(d, A, b0, b1)                                                 \
    asm volatile("mma.sync.aligned.m16n8k16.row.col.f32.f16.f16.f32 "         \
        "{%0,%1,%2,%3}, {%4,%5,%6,%7}, {%8,%9}, {%0,%1,%2,%3};"               \
        : "+f"((d)[0]), "+f"((d)[1]), "+f"((d)[2]), "+f"((d)[3])              \
        : "r"((A)[0]), "r"((A)[1]), "r"((A)[2]), "r"((A)[3]),                 \
          "r"(b0), "r"(b1))

#define CP_ASYNC16(dst, src)                                                  \
    asm volatile("cp.async.cg.shared.global [%0], [%1], 16;"                  \
        :: "r"(dst), "l"(src) : "memory")
#define CP_COMMIT()  asm volatile("cp.async.commit_group;" ::: "memory")
#define CP_WAIT0()   asm volatile("cp.async.wait_group 0;" ::: "memory")
#define CP_WAIT1()   asm volatile("cp.async.wait_group 1;" ::: "memory")

// ---------------------------------------------------------------------------
// One-time w conversion: fp32 -> fp16 (row-major). Separate kernel — at the
// DRAM roof (27us); round-12 proved fusing it into the GEMM grid regresses.
// ---------------------------------------------------------------------------
__global__ __launch_bounds__(256)
void convert_w(const float* __restrict__ w)
{
    const size_t i = (size_t)blockIdx.x * blockDim.x + threadIdx.x; // 8 floats
    const float4* w4 = (const float4*)w;
    const float4 a = w4[i * 2], b = w4[i * 2 + 1];
    ((uint4*)g_whf)[i] = make_uint4(packhf(a.x, a.y), packhf(a.z, a.w),
                                    packhf(b.x, b.y), packhf(b.z, b.w));
}

// ---------------------------------------------------------------------------
// Screening GEMM (2 CTAs/SM): fp16 HMMA, 128(M) x 64(N) x 16 tiles,
// 8 warps (4M x 2N), warp tile 32x32. A resident 32KB; B triple-buffered
// 3x16KB cp.async (wait_group 1); stage double-buffered 2x16KB.
// Measured ~248us = HMMA-issue floor (16.78M HMMA / 592 SMSP x rt 16).
// ---------------------------------------------------------------------------
#define SM_B      32768
#define SM_STAGE  81920
#define BTILE_SZ  16384
#define STAGE_SZ  16384
#define SM_TOTAL  114688

__global__ __launch_bounds__(256, 2)
void gemm_screen(const float* __restrict__ x)
{
    extern __shared__ char smem[];
    const uint32_t sb = smem_u32(smem);
    const int tid  = threadIdx.x;
    const int lane = tid & 31;
    const int wid  = tid >> 5;
    const int rowBase   = blockIdx.x * GMB;
    const int itemBase0 = blockIdx.y * (NTILE * TPB);

    int bR[4], bC[4];
    uint32_t bDst[4];
    #pragma unroll
    for (int i = 0; i < 4; i++) {
        const int flat = tid + 256 * i;
        bR[i] = flat >> 4;
        bC[i] = flat & 15;
        bDst[i] = sb + SM_B + bR[i] * 256 + ((bC[i] ^ (bR[i] & 7)) << 4);
    }

    // ---- Stage A (128x128): fp32 -> fp16, 16B-chunk XOR swizzle ----
    const float4* x4 = (const float4*)(x + (size_t)rowBase * EMBED);
    #pragma unroll
    for (int i = 0; i < 8; i++) {
        const int flat = tid + 256 * i;
        const int r = flat >> 4, c = flat & 15;
        const int swc = c ^ (r & 7);
        float4 a0 = x4[flat * 2], a1 = x4[flat * 2 + 1];
        uint4 pa = make_uint4(packhf(a0.x, a0.y), packhf(a0.z, a0.w),
                              packhf(a1.x, a1.y), packhf(a1.z, a1.w));
        *(uint4*)(smem + r * 256 + swc * 16) = pa;
    }

    // ---- cp.async B tiles 0 and 1 (two groups in flight) ----
    #pragma unroll
    for (int i = 0; i < 4; i++) {
        const char* src = (const char*)g_whf
                        + (size_t)(itemBase0 + bR[i]) * 256 + bC[i] * 16;
        CP_ASYNC16(bDst[i], src);
    }
    CP_COMMIT();
    #pragma unroll
    for (int i = 0; i < 4; i++) {
        const char* src = (const char*)g_whf
                        + (size_t)(itemBase0 + NTILE + bR[i]) * 256 + bC[i] * 16;
        CP_ASYNC16(bDst[i] + BTILE_SZ, src);
    }
    CP_COMMIT();

    const int wm = wid >> 1;
    const int wn = wid & 1;
    const int la7  = lane & 7;
    const int lg8  = (lane >> 3) & 1;
    const int cgrp = lane >> 4;

    int Aoff[2], Asw[2];
    #pragma unroll
    for (int a = 0; a < 2; a++) {
        const int rr = wm * 32 + a * 16 + la7 + lg8 * 8;
        Aoff[a] = rr * 256;  Asw[a] = rr & 7;
    }
    int BoffR[2], Bsw[2];
    #pragma unroll
    for (int p = 0; p < 2; p++) {
        const int nr = wn * 32 + p * 16 + la7 + lg8 * 8;
        BoffR[p] = nr * 256;  Bsw[p] = nr & 7;
    }
    const int smRow0 = wm * 32 + lg8 * 8 + la7;
    const int chunk0 = wn * 4 + (lane >> 4);

    for (int n = 0; n < TPB; n++) {
        const int cur3 = n % 3;
        const int itemBase = itemBase0 + n * NTILE;

        if (n == TPB - 1) CP_WAIT0(); else CP_WAIT1();
        __syncthreads();

        if (n + 2 < TPB) {
            const uint32_t flip = ((n + 2) % 3) * BTILE_SZ;
            #pragma unroll
            for (int i = 0; i < 4; i++) {
                const char* src = (const char*)g_whf
                                + (size_t)(itemBase + 2 * NTILE + bR[i]) * 256
                                + bC[i] * 16;
                CP_ASYNC16(bDst[i] + flip, src);
            }
            CP_COMMIT();
        }

        float d[2][4][4];
        #pragma unroll
        for (int a = 0; a < 2; a++)
            #pragma unroll
            for (int b = 0; b < 4; b++)
                #pragma unroll
                for (int q = 0; q < 4; q++) d[a][b][q] = 0.0f;

        const uint32_t bBase = sb + SM_B + cur3 * BTILE_SZ;
        #pragma unroll
        for (int ks = 0; ks < 8; ks++) {
            const int kc = ks * 2 + cgrp;
            uint32_t A[2][4], B[2][4];
            #pragma unroll
            for (int a = 0; a < 2; a++)
                LDSM4(A[a][0], A[a][1], A[a][2], A[a][3],
                      sb + Aoff[a] + ((kc ^ Asw[a]) << 4));
            #pragma unroll
            for (int p = 0; p < 2; p++)
                LDSM4(B[p][0], B[p][1], B[p][2], B[p][3],
                      bBase + BoffR[p] + ((kc ^ Bsw[p]) << 4));
            #pragma unroll
            for (int a = 0; a < 2; a++)
                #pragma unroll
                for (int b = 0; b < 4; b++)
                    MMA_F16(d[a][b], A[a], B[b >> 1][b & 1], B[b >> 1][(b & 1) + 2]);
        }

        const uint32_t stageBase = sb + SM_STAGE + (n & 1) * STAGE_SZ;
        const int colW = itemBase + wn * 32;
        #pragma unroll
        for (int a = 0; a < 2; a++) {
            uint32_t p[8];
            float m1 = -3.402823466e+38f, m2 = m1;
            #pragma unroll
            for (int b = 0; b < 4; b++) {
                p[b * 2 + 0] = packhf(d[a][b][0], d[a][b][1]);
                p[b * 2 + 1] = packhf(d[a][b][2], d[a][b][3]);
                m1 = fmaxf(m1, fmaxf(d[a][b][0], d[a][b][1]));
                m2 = fmaxf(m2, fmaxf(d[a][b][2], d[a][b][3]));
            }
            const int row = smRow0 + a * 16;
            #pragma unroll
            for (int bp = 0; bp < 2; bp++) {
                const int ch = chunk0 + bp * 2;
                const uint32_t addr = stageBase + row * 128
                                    + ((ch ^ (row & 7)) << 4);
                STSM4(addr, p[bp * 4 + 0], p[bp * 4 + 1],
                            p[bp * 4 + 2], p[bp * 4 + 3]);
            }
            m1 = fmaxf(m1, __shfl_xor_sync(0xFFFFFFFFu, m1, 1));
            m1 = fmaxf(m1, __shfl_xor_sync(0xFFFFFFFFu, m1, 2));
            m2 = fmaxf(m2, __shfl_xor_sync(0xFFFFFFFFu, m2, 1));
            m2 = fmaxf(m2, __shfl_xor_sync(0xFFFFFFFFu, m2, 2));
            if ((lane & 3) == 0) {
                const int r1 = rowBase + wm * 32 + a * 16 + (lane >> 2);
                const int grp = colW / TM;
                g_tilemax[(size_t)r1 * NTM + grp]       = m1;
                g_tilemax[(size_t)(r1 + 8) * NTM + grp] = m2;
            }
        }

        if (n >= 1) {
            const char* prev = smem + SM_STAGE + ((n - 1) & 1) * STAGE_SZ;
            const int ib = itemBase - NTILE;
            #pragma unroll
            for (int i = 0; i < 4; i++) {
                const int flat = tid + 256 * i;
                const int r = flat >> 3, c = flat & 7;
                const uint4 v = *(const uint4*)(prev + r * 128
                                                + ((c ^ (r & 7)) << 4));
                *(uint4*)((char*)g_logits
                          + ((size_t)(rowBase + r) * ITEMS + ib) * 2
                          + c * 16) = v;
            }
        }
    }

    __syncthreads();
    {
        const char* prev = smem + SM_STAGE + ((TPB - 1) & 1) * STAGE_SZ;
        const int ib = itemBase0 + (TPB - 1) * NTILE;
        #pragma unroll
        for (int i = 0; i < 4; i++) {
            const int flat = tid + 256 * i;
            const int r = flat >> 3, c = flat & 7;
            const uint4 v = *(const uint4*)(prev + r * 128
                                            + ((c ^ (r & 7)) << 4));
            *(uint4*)((char*)g_logits
                      + ((size_t)(rowBase + r) * ITEMS + ib) * 2
                      + c * 16) = v;
        }
    }
}

// ---------------------------------------------------------------------------
// Top-k: 512 threads, 4 CTAs/SM (__launch_bounds__(512,4) => regs <= 32) —
// the measured optimum (round 14; both 3-CTA and 8-CTA variants are slower).
// fp16 screen error bound B = 2^-11 * ||x||2 * 0.1*sqrt(128); eps = 2.1*B;
// threshold via bisection (16 iters) on 512 group maxima (16 tiles each) with
// invariant cnt(>= lo) >= 100; thr = lo - 1.05*eps; exact sequential-fmaf
// rescore (reference accumulation order); 64-bit key bitonic sort
// (value desc, index asc on ties — matches jax.lax.top_k).
// ---------------------------------------------------------------------------
#define TKT  512
#define CMAX 1024

__device__ __forceinline__ unsigned int fkey(float f) {
    unsigned int b = __float_as_uint(f);
    return b ^ ((b & 0x80000000u) ? 0xFFFFFFFFu : 0x80000000u);
}

__device__ __forceinline__ int wagg_append(int* ctr, bool pred, int ln) {
    const unsigned mask = __ballot_sync(0xFFFFFFFFu, pred);
    if (!pred) return -1;
    const int leader = __ffs(mask) - 1;
    int base = 0;
    if (ln == leader) base = atomicAdd(ctr, __popc(mask));
    base = __shfl_sync(mask, base, leader);
    return base + __popc(mask & ((1u << ln) - 1u));
}

__global__ __launch_bounds__(TKT, 4)
void topk_kernel(const float* __restrict__ x, const float* __restrict__ w,
                 float* __restrict__ out)
{
    __shared__ float              s_x[EMBED];
    __shared__ float              s_wmax[16], s_wmin[16];
    __shared__ int                s_tiles[CMAX];
    __shared__ int                s_cidx[CMAX];
    __shared__ unsigned long long s_cand[CMAX];
    __shared__ int   s_nt, s_nc;
    __shared__ float s_eps;

    const int row = blockIdx.x;
    const int tid = threadIdx.x;
    const int wrp = tid >> 5, ln = tid & 31;
    const float4* tm4 = (const float4*)(g_tilemax + (size_t)row * NTM);

    if (tid < EMBED) s_x[tid] = x[(size_t)row * EMBED + tid];
    if (tid == 0) { s_nt = 0; s_nc = 0; }
    __syncthreads();

    if (tid < 32) {
        float ss = 0.0f;
        #pragma unroll
        for (int j = 0; j < 4; j++) { float v = s_x[tid * 4 + j]; ss += v * v; }
        #pragma unroll
        for (int o = 16; o > 0; o >>= 1) ss += __shfl_xor_sync(0xFFFFFFFFu, ss, o);
        if (tid == 0) s_eps = 1.05f * (1.0f / 1024.0f) * sqrtf(ss) * 1.1313708f;
    }

    // per-thread group max over 16 contiguous tile-maxima (4 x LDG.128)
    float m = -3.402823466e+38f;
    #pragma unroll
    for (int j = 0; j < 4; j++) {
        const float4 v = tm4[tid * 4 + j];
        m = fmaxf(m, fmaxf(fmaxf(v.x, v.y), fmaxf(v.z, v.w)));
    }
    float wmx = m, wmn = m;
    #pragma unroll
    for (int o = 16; o > 0; o >>= 1) {
        wmx = fmaxf(wmx, __shfl_xor_sync(0xFFFFFFFFu, wmx, o));
        wmn = fminf(wmn, __shfl_xor_sync(0xFFFFFFFFu, wmn, o));
    }
    if (ln == 0) { s_wmax[wrp] = wmx; s_wmin[wrp] = wmn; }
    __syncthreads();
    float hi = s_wmax[0], lo = s_wmin[0];
    #pragma unroll
    for (int j = 1; j < 16; j++) {
        hi = fmaxf(hi, s_wmax[j]);
        lo = fminf(lo, s_wmin[j]);
    }

    // bisection: invariant cnt(m >= lo) >= 100; a lower lo only ADDS
    // candidates (still exact); resolution after 16 iters << eps
    #pragma unroll
    for (int it = 0; it < 16; it++) {
        const float mid = 0.5f * (lo + hi);
        const int cnt = __syncthreads_count(m >= mid);
        if (cnt >= TOPK) lo = mid; else hi = mid;
    }
    const float thr = lo - 1.05f * s_eps - 1e-6f;

    // qualifying tiles (warp-aggregated append)
    #pragma unroll
    for (int j = 0; j < 4; j++) {
        const float4 v = tm4[tid * 4 + j];
        const int base = tid * 16 + j * 4;
        #pragma unroll
        for (int c = 0; c < 4; c++) {
            const float tv = (c == 0) ? v.x : (c == 1) ? v.y : (c == 2) ? v.z : v.w;
            const bool q = (tv >= thr);
            const int p = wagg_append(&s_nt, q, ln);
            if (q && p < CMAX) s_tiles[p] = base + c;
        }
    }
    __syncthreads();
    const int ntl = s_nt < CMAX ? s_nt : CMAX;

    // candidates within qualifying tiles: 4-way MLP over tiles per warp
    const __half* lg = g_logits + (size_t)row * ITEMS;
    const int NW = TKT / 32;
    int i = wrp;
    for (; i + 3 * NW < ntl; i += 4 * NW) {
        int t0 = s_tiles[i],          t1 = s_tiles[i + NW];
        int t2 = s_tiles[i + 2 * NW], t3 = s_tiles[i + 3 * NW];
        float v0 = __half2float(lg[t0 * TM + ln]);
        float v1 = __half2float(lg[t1 * TM + ln]);
        float v2 = __half2float(lg[t2 * TM + ln]);
        float v3 = __half2float(lg[t3 * TM + ln]);
        bool q; int p;
        q = (v0 >= thr); p = wagg_append(&s_nc, q, ln);
        if (q && p < CMAX) s_cidx[p] = t0 * TM + ln;
        q = (v1 >= thr); p = wagg_append(&s_nc, q, ln);
        if (q && p < CMAX) s_cidx[p] = t1 * TM + ln;
        q = (v2 >= thr); p = wagg_append(&s_nc, q, ln);
        if (q && p < CMAX) s_cidx[p] = t2 * TM + ln;
        q = (v3 >= thr); p = wagg_append(&s_nc, q, ln);
        if (q && p < CMAX) s_cidx[p] = t3 * TM + ln;
    }
    for (; i < ntl; i += NW) {
        const int idx = s_tiles[i] * TM + ln;
        const float v = __half2float(lg[idx]);
        const bool q = (v >= thr);
        const int p = wagg_append(&s_nc, q, ln);
        if (q && p < CMAX) s_cidx[p] = idx;
    }
    __syncthreads();
    const int C = s_nc < CMAX ? s_nc : CMAX;

    // exact rescore: one thread per candidate, sequential fmaf k=0..127
    for (int i2 = tid; i2 < C; i2 += TKT) {
        const int idx = s_cidx[i2];
        const float* wr = w + (size_t)idx * EMBED;
        float s = 0.0f;
        #pragma unroll 8
        for (int k4 = 0; k4 < EMBED / 4; k4++) {
            const float4 wv = ((const float4*)wr)[k4];
            s = fmaf(s_x[k4 * 4 + 0], wv.x, s);
            s = fmaf(s_x[k4 * 4 + 1], wv.y, s);
            s = fmaf(s_x[k4 * 4 + 2], wv.z, s);
            s = fmaf(s_x[k4 * 4 + 3], wv.w, s);
        }
        s_cand[i2] = ((unsigned long long)fkey(s) << 32) |
                     (unsigned int)(~(unsigned int)idx);
    }
    __syncthreads();

    int P = 128;
    while (P < C) P <<= 1;
    for (int i2 = tid; i2 < P; i2 += TKT)
        if (i2 >= C) s_cand[i2] = 0ULL;
    __syncthreads();

    // bitonic sort P 64-bit keys desc (value desc, index asc on ties)
    for (int k = 2; k <= P; k <<= 1) {
        for (int j = k >> 1; j > 0; j >>= 1) {
            for (int i2 = tid; i2 < P; i2 += TKT) {
                const int ixj = i2 ^ j;
                if (ixj > i2) {
                    const bool desc = ((i2 & k) == 0);
                    const unsigned long long a = s_cand[i2], b = s_cand[ixj];
                    if (desc ? (a < b) : (a > b)) { s_cand[i2] = b; s_cand[ixj] = a; }
                }
            }
            __syncthreads();
        }
    }

    if (tid < TOPK) {
        const unsigned int low = (unsigned int)s_cand[tid];
        out[(size_t)row * TOPK + tid] = (float)(~low);
    }
}

// ---------------------------------------------------------------------------
extern "C" void kernel_launch(void* const* d_in, const int* in_sizes, int n_in,
                              void* d_out, int out_size)
{
    const float* x = nullptr;
    const float* w = nullptr;
    for (int i = 0; i < n_in; i++) {
        if (in_sizes[i] == BATCH * EMBED)      x = (const float*)d_in[i];
        else if (in_sizes[i] == ITEMS * EMBED) w = (const float*)d_in[i];
    }
    float* out = (float*)d_out;

    static bool attr_set = false;
    if (!attr_set) {
        cudaFuncSetAttribute(gemm_screen,
                             cudaFuncAttributeMaxDynamicSharedMemorySize, SM_TOTAL);
        attr_set = true;
    }

    convert_w<<<(ITEMS * EMBED / 8) / 256, 256>>>(w);
    dim3 grid(BATCH / GMB, ITEMS / (NTILE * TPB));   // (8, 256)
    gemm_screen<<<grid, 256, SM_TOTAL>>>(x);
    topk_kernel<<<BATCH, TKT>>>(x, w, out);
}

// round 17
// speedup vs baseline: 1.0170x; 1.0009x over previous
#include <cuda_runtime.h>
#include <cuda_fp16.h>
#include <cstdint>

#define BATCH    1024
#define EMBED    128
#define ITEMS    262144
#define TOPK     100
#define TM       32               // tile-max granularity (items)
#define NTM      (ITEMS/TM)       // 8192 tile maxima per row

#define NTILE    64               // items per GEMM N-tile
#define TPB      16               // N-tiles per CTA
#define GMB      128              // M rows per CTA

__device__ __half g_logits[(size_t)BATCH * ITEMS];
__device__ float  g_tilemax[(size_t)BATCH * NTM];
__device__ __half g_whf[(size_t)ITEMS * EMBED];   // pre-converted w (fp16)

// ---------------------------------------------------------------------------
__device__ __forceinline__ uint32_t smem_u32(const void* p) {
    uint32_t a;
    asm("{ .reg .u64 t; cvta.to.shared.u64 t, %1; cvt.u32.u64 %0, t; }"
        : "=r"(a) : "l"(p));
    return a;
}
__device__ __forceinline__ uint32_t packhf(float lo, float hi) {
    uint32_t r;
    asm("cvt.rn.f16x2.f32 %0, %1, %2;" : "=r"(r) : "f"(hi), "f"(lo));
    return r;
}

#define LDSM4(r0, r1, r2, r3, a)                                              \
    asm volatile("ldmatrix.sync.aligned.m8n8.x4.shared.b16 {%0,%1,%2,%3}, [%4];" \
        : "=r"(r0), "=r"(r1), "=r"(r2), "=r"(r3) : "r"(a))

#define STSM4(a, r0, r1, r2, r3)                                              \
    asm volatile("stmatrix.sync.aligned.m8n8.x4.shared.b16 [%0], {%1,%2,%3,%4};" \
        :: "r"(a), "r"(r0), "r"(r1), "r"(r2), "r"(r3) : "memory")

#define MMA_F16(d, A, b0, b1)                                                 \
    asm volatile("mma.sync.aligned.m16n8k16.row.col.f32.f16.f16.f32 "         \
        "{%0,%1,%2,%3}, {%4,%5,%6,%7}, {%8,%9}, {%0,%1,%2,%3};"               \
        : "+f"((d)[0]), "+f"((d)[1]), "+f"((d)[2]), "+f"((d)[3])              \
        : "r"((A)[0]), "r"((A)[1]), "r"((A)[2]), "r"((A)[3]),                 \
          "r"(b0), "r"(b1))

#define CP_ASYNC16(dst, src)                                                  \
    asm volatile("cp.async.cg.shared.global [%0], [%1], 16;"                  \
        :: "r"(dst), "l"(src) : "memory")
#define CP_COMMIT()  asm volatile("cp.async.commit_group;" ::: "memory")
#define CP_WAIT0()   asm volatile("cp.async.wait_group 0;" ::: "memory")
#define CP_WAIT1()   asm volatile("cp.async.wait_group 1;" ::: "memory")

// ---------------------------------------------------------------------------
// One-time w conversion: fp32 -> fp16 (row-major). Separate kernel — at the
// DRAM roof (27us); round-12 proved fusing it into the GEMM grid regresses.
// ---------------------------------------------------------------------------
__global__ __launch_bounds__(256)
void convert_w(const float* __restrict__ w)
{
    const size_t i = (size_t)blockIdx.x * blockDim.x + threadIdx.x; // 8 floats
    const float4* w4 = (const float4*)w;
    const float4 a = w4[i * 2], b = w4[i * 2 + 1];
    ((uint4*)g_whf)[i] = make_uint4(packhf(a.x, a.y), packhf(a.z, a.w),
                                    packhf(b.x, b.y), packhf(b.z, b.w));
}

// ---------------------------------------------------------------------------
// Screening GEMM (2 CTAs/SM): fp16 HMMA, 128(M) x 64(N) x 16 tiles,
// 8 warps (4M x 2N), warp tile 32x32. A resident 32KB; B triple-buffered
// 3x16KB cp.async (wait_group 1); stage double-buffered 2x16KB.
// Measured ~248us = HMMA-issue floor (16.78M HMMA / 592 SMSP x rt 16).
// ---------------------------------------------------------------------------
#define SM_B      32768
#define SM_STAGE  81920
#define BTILE_SZ  16384
#define STAGE_SZ  16384
#define SM_TOTAL  114688

__global__ __launch_bounds__(256, 2)
void gemm_screen(const float* __restrict__ x)
{
    extern __shared__ char smem[];
    const uint32_t sb = smem_u32(smem);
    const int tid  = threadIdx.x;
    const int lane = tid & 31;
    const int wid  = tid >> 5;
    const int rowBase   = blockIdx.x * GMB;
    const int itemBase0 = blockIdx.y * (NTILE * TPB);

    int bR[4], bC[4];
    uint32_t bDst[4];
    #pragma unroll
    for (int i = 0; i < 4; i++) {
        const int flat = tid + 256 * i;
        bR[i] = flat >> 4;
        bC[i] = flat & 15;
        bDst[i] = sb + SM_B + bR[i] * 256 + ((bC[i] ^ (bR[i] & 7)) << 4);
    }

    // ---- Stage A (128x128): fp32 -> fp16, 16B-chunk XOR swizzle ----
    const float4* x4 = (const float4*)(x + (size_t)rowBase * EMBED);
    #pragma unroll
    for (int i = 0; i < 8; i++) {
        const int flat = tid + 256 * i;
        const int r = flat >> 4, c = flat & 15;
        const int swc = c ^ (r & 7);
        float4 a0 = x4[flat * 2], a1 = x4[flat * 2 + 1];
        uint4 pa = make_uint4(packhf(a0.x, a0.y), packhf(a0.z, a0.w),
                              packhf(a1.x, a1.y), packhf(a1.z, a1.w));
        *(uint4*)(smem + r * 256 + swc * 16) = pa;
    }

    // ---- cp.async B tiles 0 and 1 (two groups in flight) ----
    #pragma unroll
    for (int i = 0; i < 4; i++) {
        const char* src = (const char*)g_whf
                        + (size_t)(itemBase0 + bR[i]) * 256 + bC[i] * 16;
        CP_ASYNC16(bDst[i], src);
    }
    CP_COMMIT();
    #pragma unroll
    for (int i = 0; i < 4; i++) {
        const char* src = (const char*)g_whf
                        + (size_t)(itemBase0 + NTILE + bR[i]) * 256 + bC[i] * 16;
        CP_ASYNC16(bDst[i] + BTILE_SZ, src);
    }
    CP_COMMIT();

    const int wm = wid >> 1;
    const int wn = wid & 1;
    const int la7  = lane & 7;
    const int lg8  = (lane >> 3) & 1;
    const int cgrp = lane >> 4;

    int Aoff[2], Asw[2];
    #pragma unroll
    for (int a = 0; a < 2; a++) {
        const int rr = wm * 32 + a * 16 + la7 + lg8 * 8;
        Aoff[a] = rr * 256;  Asw[a] = rr & 7;
    }
    int BoffR[2], Bsw[2];
    #pragma unroll
    for (int p = 0; p < 2; p++) {
        const int nr = wn * 32 + p * 16 + la7 + lg8 * 8;
        BoffR[p] = nr * 256;  Bsw[p] = nr & 7;
    }
    const int smRow0 = wm * 32 + lg8 * 8 + la7;
    const int chunk0 = wn * 4 + (lane >> 4);

    for (int n = 0; n < TPB; n++) {
        const int cur3 = n % 3;
        const int itemBase = itemBase0 + n * NTILE;

        if (n == TPB - 1) CP_WAIT0(); else CP_WAIT1();
        __syncthreads();

        if (n + 2 < TPB) {
            const uint32_t flip = ((n + 2) % 3) * BTILE_SZ;
            #pragma unroll
            for (int i = 0; i < 4; i++) {
                const char* src = (const char*)g_whf
                                + (size_t)(itemBase + 2 * NTILE + bR[i]) * 256
                                + bC[i] * 16;
                CP_ASYNC16(bDst[i] + flip, src);
            }
            CP_COMMIT();
        }

        float d[2][4][4];
        #pragma unroll
        for (int a = 0; a < 2; a++)
            #pragma unroll
            for (int b = 0; b < 4; b++)
                #pragma unroll
                for (int q = 0; q < 4; q++) d[a][b][q] = 0.0f;

        const uint32_t bBase = sb + SM_B + cur3 * BTILE_SZ;
        #pragma unroll
        for (int ks = 0; ks < 8; ks++) {
            const int kc = ks * 2 + cgrp;
            uint32_t A[2][4], B[2][4];
            #pragma unroll
            for (int a = 0; a < 2; a++)
                LDSM4(A[a][0], A[a][1], A[a][2], A[a][3],
                      sb + Aoff[a] + ((kc ^ Asw[a]) << 4));
            #pragma unroll
            for (int p = 0; p < 2; p++)
                LDSM4(B[p][0], B[p][1], B[p][2], B[p][3],
                      bBase + BoffR[p] + ((kc ^ Bsw[p]) << 4));
            #pragma unroll
            for (int a = 0; a < 2; a++)
                #pragma unroll
                for (int b = 0; b < 4; b++)
                    MMA_F16(d[a][b], A[a], B[b >> 1][b & 1], B[b >> 1][(b & 1) + 2]);
        }

        const uint32_t stageBase = sb + SM_STAGE + (n & 1) * STAGE_SZ;
        const int colW = itemBase + wn * 32;
        #pragma unroll
        for (int a = 0; a < 2; a++) {
            uint32_t p[8];
            float m1 = -3.402823466e+38f, m2 = m1;
            #pragma unroll
            for (int b = 0; b < 4; b++) {
                p[b * 2 + 0] = packhf(d[a][b][0], d[a][b][1]);
                p[b * 2 + 1] = packhf(d[a][b][2], d[a][b][3]);
                m1 = fmaxf(m1, fmaxf(d[a][b][0], d[a][b][1]));
                m2 = fmaxf(m2, fmaxf(d[a][b][2], d[a][b][3]));
            }
            const int row = smRow0 + a * 16;
            #pragma unroll
            for (int bp = 0; bp < 2; bp++) {
                const int ch = chunk0 + bp * 2;
                const uint32_t addr = stageBase + row * 128
                                    + ((ch ^ (row & 7)) << 4);
                STSM4(addr, p[bp * 4 + 0], p[bp * 4 + 1],
                            p[bp * 4 + 2], p[bp * 4 + 3]);
            }
            m1 = fmaxf(m1, __shfl_xor_sync(0xFFFFFFFFu, m1, 1));
            m1 = fmaxf(m1, __shfl_xor_sync(0xFFFFFFFFu, m1, 2));
            m2 = fmaxf(m2, __shfl_xor_sync(0xFFFFFFFFu, m2, 1));
            m2 = fmaxf(m2, __shfl_xor_sync(0xFFFFFFFFu, m2, 2));
            if ((lane & 3) == 0) {
                const int r1 = rowBase + wm * 32 + a * 16 + (lane >> 2);
                const int grp = colW / TM;
                g_tilemax[(size_t)r1 * NTM + grp]       = m1;
                g_tilemax[(size_t)(r1 + 8) * NTM + grp] = m2;
            }
        }

        if (n >= 1) {
            const char* prev = smem + SM_STAGE + ((n - 1) & 1) * STAGE_SZ;
            const int ib = itemBase - NTILE;
            #pragma unroll
            for (int i = 0; i < 4; i++) {
                const int flat = tid + 256 * i;
                const int r = flat >> 3, c = flat & 7;
                const uint4 v = *(const uint4*)(prev + r * 128
                                                + ((c ^ (r & 7)) << 4));
                *(uint4*)((char*)g_logits
                          + ((size_t)(rowBase + r) * ITEMS + ib) * 2
                          + c * 16) = v;
            }
        }
    }

    __syncthreads();
    {
        const char* prev = smem + SM_STAGE + ((TPB - 1) & 1) * STAGE_SZ;
        const int ib = itemBase0 + (TPB - 1) * NTILE;
        #pragma unroll
        for (int i = 0; i < 4; i++) {
            const int flat = tid + 256 * i;
            const int r = flat >> 3, c = flat & 7;
            const uint4 v = *(const uint4*)(prev + r * 128
                                            + ((c ^ (r & 7)) << 4));
            *(uint4*)((char*)g_logits
                      + ((size_t)(rowBase + r) * ITEMS + ib) * 2
                      + c * 16) = v;
        }
    }
}

// ---------------------------------------------------------------------------
// Top-k: 512 threads, 4 CTAs/SM (__launch_bounds__(512,4) => regs <= 32) —
// the measured optimum (rounds 13-16; 3-CTA and 8-CTA variants both slower).
// fp16 screen error bound B = 2^-11 * ||x||2 * 0.1*sqrt(128); eps = 2.1*B;
// threshold via bisection (14 iters) on 512 group maxima (16 tiles each) with
// invariant cnt(>= lo) >= 100; coarser lo only ADDS candidates (still exact);
// thr = lo - 1.05*eps; exact sequential-fmaf rescore (reference accumulation
// order); 64-bit key bitonic sort (value desc, index asc on ties).
// ---------------------------------------------------------------------------
#define TKT  512
#define CMAX 1024

__device__ __forceinline__ unsigned int fkey(float f) {
    unsigned int b = __float_as_uint(f);
    return b ^ ((b & 0x80000000u) ? 0xFFFFFFFFu : 0x80000000u);
}

__device__ __forceinline__ int wagg_append(int* ctr, bool pred, int ln) {
    const unsigned mask = __ballot_sync(0xFFFFFFFFu, pred);
    if (!pred) return -1;
    const int leader = __ffs(mask) - 1;
    int base = 0;
    if (ln == leader) base = atomicAdd(ctr, __popc(mask));
    base = __shfl_sync(mask, base, leader);
    return base + __popc(mask & ((1u << ln) - 1u));
}

__global__ __launch_bounds__(TKT, 4)
void topk_kernel(const float* __restrict__ x, const float* __restrict__ w,
                 float* __restrict__ out)
{
    __shared__ float              s_x[EMBED];
    __shared__ float              s_wmax[16], s_wmin[16];
    __shared__ int                s_tiles[CMAX];
    __shared__ int                s_cidx[CMAX];
    __shared__ unsigned long long s_cand[CMAX];
    __shared__ int   s_nt, s_nc;
    __shared__ float s_eps;

    const int row = blockIdx.x;
    const int tid = threadIdx.x;
    const int wrp = tid >> 5, ln = tid & 31;
    const float4* tm4 = (const float4*)(g_tilemax + (size_t)row * NTM);

    if (tid < EMBED) s_x[tid] = x[(size_t)row * EMBED + tid];
    if (tid == 0) { s_nt = 0; s_nc = 0; }
    __syncthreads();

    if (tid < 32) {
        float ss = 0.0f;
        #pragma unroll
        for (int j = 0; j < 4; j++) { float v = s_x[tid * 4 + j]; ss += v * v; }
        #pragma unroll
        for (int o = 16; o > 0; o >>= 1) ss += __shfl_xor_sync(0xFFFFFFFFu, ss, o);
        if (tid == 0) s_eps = 1.05f * (1.0f / 1024.0f) * sqrtf(ss) * 1.1313708f;
    }

    // per-thread group max over 16 contiguous tile-maxima (4 x LDG.128)
    float m = -3.402823466e+38f;
    #pragma unroll
    for (int j = 0; j < 4; j++) {
        const float4 v = tm4[tid * 4 + j];
        m = fmaxf(m, fmaxf(fmaxf(v.x, v.y), fmaxf(v.z, v.w)));
    }
    float wmx = m, wmn = m;
    #pragma unroll
    for (int o = 16; o > 0; o >>= 1) {
        wmx = fmaxf(wmx, __shfl_xor_sync(0xFFFFFFFFu, wmx, o));
        wmn = fminf(wmn, __shfl_xor_sync(0xFFFFFFFFu, wmn, o));
    }
    if (ln == 0) { s_wmax[wrp] = wmx; s_wmin[wrp] = wmn; }
    __syncthreads();
    float hi = s_wmax[0], lo = s_wmin[0];
    #pragma unroll
    for (int j = 1; j < 16; j++) {
        hi = fmaxf(hi, s_wmax[j]);
        lo = fminf(lo, s_wmin[j]);
    }

    // bisection: invariant cnt(m >= lo) >= 100; resolution after 14 iters
    // ((hi-lo)/16384) << eps; a coarser lo only ADDS candidates (still exact)
    #pragma unroll
    for (int it = 0; it < 14; it++) {
        const float mid = 0.5f * (lo + hi);
        const int cnt = __syncthreads_count(m >= mid);
        if (cnt >= TOPK) lo = mid; else hi = mid;
    }
    const float thr = lo - 1.05f * s_eps - 1e-6f;

    // qualifying tiles (warp-aggregated append)
    #pragma unroll
    for (int j = 0; j < 4; j++) {
        const float4 v = tm4[tid * 4 + j];
        const int base = tid * 16 + j * 4;
        #pragma unroll
        for (int c = 0; c < 4; c++) {
            const float tv = (c == 0) ? v.x : (c == 1) ? v.y : (c == 2) ? v.z : v.w;
            const bool q = (tv >= thr);
            const int p = wagg_append(&s_nt, q, ln);
            if (q && p < CMAX) s_tiles[p] = base + c;
        }
    }
    __syncthreads();
    const int ntl = s_nt < CMAX ? s_nt : CMAX;

    // candidates within qualifying tiles: 4-way MLP over tiles per warp
    const __half* lg = g_logits + (size_t)row * ITEMS;
    const int NW = TKT / 32;
    int i = wrp;
    for (; i + 3 * NW < ntl; i += 4 * NW) {
        int t0 = s_tiles[i],          t1 = s_tiles[i + NW];
        int t2 = s_tiles[i + 2 * NW], t3 = s_tiles[i + 3 * NW];
        float v0 = __half2float(lg[t0 * TM + ln]);
        float v1 = __half2float(lg[t1 * TM + ln]);
        float v2 = __half2float(lg[t2 * TM + ln]);
        float v3 = __half2float(lg[t3 * TM + ln]);
        bool q; int p;
        q = (v0 >= thr); p = wagg_append(&s_nc, q, ln);
        if (q && p < CMAX) s_cidx[p] = t0 * TM + ln;
        q = (v1 >= thr); p = wagg_append(&s_nc, q, ln);
        if (q && p < CMAX) s_cidx[p] = t1 * TM + ln;
        q = (v2 >= thr); p = wagg_append(&s_nc, q, ln);
        if (q && p < CMAX) s_cidx[p] = t2 * TM + ln;
        q = (v3 >= thr); p = wagg_append(&s_nc, q, ln);
        if (q && p < CMAX) s_cidx[p] = t3 * TM + ln;
    }
    for (; i < ntl; i += NW) {
        const int idx = s_tiles[i] * TM + ln;
        const float v = __half2float(lg[idx]);
        const bool q = (v >= thr);
        const int p = wagg_append(&s_nc, q, ln);
        if (q && p < CMAX) s_cidx[p] = idx;
    }
    __syncthreads();
    const int C = s_nc < CMAX ? s_nc : CMAX;

    // exact rescore: one thread per candidate, sequential fmaf k=0..127
    for (int i2 = tid; i2 < C; i2 += TKT) {
        const int idx = s_cidx[i2];
        const float* wr = w + (size_t)idx * EMBED;
        float s = 0.0f;
        #pragma unroll 8
        for (int k4 = 0; k4 < EMBED / 4; k4++) {
            const float4 wv = ((const float4*)wr)[k4];
            s = fmaf(s_x[k4 * 4 + 0], wv.x, s);
            s = fmaf(s_x[k4 * 4 + 1], wv.y, s);
            s = fmaf(s_x[k4 * 4 + 2], wv.z, s);
            s = fmaf(s_x[k4 * 4 + 3], wv.w, s);
        }
        s_cand[i2] = ((unsigned long long)fkey(s) << 32) |
                     (unsigned int)(~(unsigned int)idx);
    }
    __syncthreads();

    int P = 128;
    while (P < C) P <<= 1;
    for (int i2 = tid; i2 < P; i2 += TKT)
        if (i2 >= C) s_cand[i2] = 0ULL;
    __syncthreads();

    // bitonic sort P 64-bit keys desc (value desc, index asc on ties)
    for (int k = 2; k <= P; k <<= 1) {
        for (int j = k >> 1; j > 0; j >>= 1) {
            for (int i2 = tid; i2 < P; i2 += TKT) {
                const int ixj = i2 ^ j;
                if (ixj > i2) {
                    const bool desc = ((i2 & k) == 0);
                    const unsigned long long a = s_cand[i2], b = s_cand[ixj];
                    if (desc ? (a < b) : (a > b)) { s_cand[i2] = b; s_cand[ixj] = a; }
                }
            }
            __syncthreads();
        }
    }

    if (tid < TOPK) {
        const unsigned int low = (unsigned int)s_cand[tid];
        out[(size_t)row * TOPK + tid] = (float)(~low);
    }
}

// ---------------------------------------------------------------------------
extern "C" void kernel_launch(void* const* d_in, const int* in_sizes, int n_in,
                              void* d_out, int out_size)
{
    const float* x = nullptr;
    const float* w = nullptr;
    for (int i = 0; i < n_in; i++) {
        if (in_sizes[i] == BATCH * EMBED)      x = (const float*)d_in[i];
        else if (in_sizes[i] == ITEMS * EMBED) w = (const float*)d_in[i];
    }
    float* out = (float*)d_out;

    static bool attr_set = false;
    if (!attr_set) {
        cudaFuncSetAttribute(gemm_screen,
                             cudaFuncAttributeMaxDynamicSharedMemorySize, SM_TOTAL);
        attr_set = true;
    }

    convert_w<<<(ITEMS * EMBED / 8) / 256, 256>>>(w);
    dim3 grid(BATCH / GMB, ITEMS / (NTILE * TPB));   // (8, 256)
    gemm_screen<<<grid, 256, SM_TOTAL>>>(x);
    topk_kernel<<<BATCH, TKT>>>(x, w, out);
}